// round 7
// baseline (speedup 1.0000x reference)
#include <cuda_runtime.h>
#include <math.h>

typedef unsigned long long u64;

__device__ __forceinline__ void upk2(u64 v, float& lo, float& hi) {
    asm("mov.b64 {%0, %1}, %2;" : "=f"(lo), "=f"(hi) : "l"(v));
}
__device__ __forceinline__ u64 pk2(float lo, float hi) {
    u64 r; asm("mov.b64 %0, {%1, %2};" : "=l"(r) : "f"(lo), "f"(hi)); return r;
}
__device__ __forceinline__ u64 fma2(u64 a, u64 b, u64 c) {
    u64 d; asm("fma.rn.f32x2 %0, %1, %2, %3;" : "=l"(d) : "l"(a), "l"(b), "l"(c)); return d;
}
__device__ __forceinline__ u64 add2(u64 a, u64 b) {
    u64 d; asm("add.rn.f32x2 %0, %1, %2;" : "=l"(d) : "l"(a), "l"(b)); return d;
}
__device__ __forceinline__ float ex2f(float x) {
    float e; asm("ex2.approx.ftz.f32 %0, %1;" : "=f"(e) : "f"(x)); return e;
}

#define MAGIC_F 12582912.0f   // 1.5 * 2^23

// Mainloop body over all N samples; ADD_AM2 selects the slow (3-op dot) path.
// Packed operands come straight out of smem as u64 pairs (no pack movs).
template <bool ADD_AM2>
__device__ __forceinline__ float kde_loop(
    const ulonglong2* __restrict__ hx,
    const ulonglong2* __restrict__ hy,
    const ulonglong2* __restrict__ hs,
    u64 qx2, u64 qy2, u64 am22, int nq)
{
    // exp2 poly coeffs (deg 5 on [-0.5, 0.5]) packed
    const u64 C0 = pk2(1.0f, 1.0f);
    const u64 C1 = pk2(0.69314718056f, 0.69314718056f);
    const u64 C2 = pk2(0.24022650696f, 0.24022650696f);
    const u64 C3 = pk2(0.05550410866f, 0.05550410866f);
    const u64 C4 = pk2(0.00961812911f, 0.00961812911f);
    const u64 C5 = pk2(0.00133335581f, 0.00133335581f);
    const u64 MG   = pk2(MAGIC_F, MAGIC_F);
    const u64 NMG  = pk2(-MAGIC_F, -MAGIC_F);
    const u64 NONE = pk2(-1.0f, -1.0f);

    float sA = 0.f, sB = 0.f, sC = 0.f, sD = 0.f, sE = 0.f, sF = 0.f;
    u64 accP = 0ull;

    #pragma unroll 4
    for (int q = 0; q < nq; q++) {
        int j = 2 * q;
        ulonglong2 X0 = hx[j], X1 = hx[j + 1];
        ulonglong2 Y0 = hy[j], Y1 = hy[j + 1];
        ulonglong2 S0 = hs[j], S1 = hs[j + 1];

        // dot products: 2 packed fma per pair (3rd add only on slow path)
        u64 ta = fma2(qx2, X0.x, S0.x); ta = fma2(qy2, Y0.x, ta);
        u64 tb = fma2(qx2, X0.y, S0.y); tb = fma2(qy2, Y0.y, tb);
        u64 tc = fma2(qx2, X1.x, S1.x); tc = fma2(qy2, Y1.x, tc);
        u64 td = fma2(qx2, X1.y, S1.y); td = fma2(qy2, Y1.y, td);
        if (ADD_AM2) {
            ta = add2(ta, am22);
            tb = add2(tb, am22);
            tc = add2(tc, am22);
            td = add2(td, am22);
        }

        // 3 pairs via MUFU ex2, scalar-FADD accumulate (no pack movs)
        float a0, a1, b0, b1, c0, c1;
        upk2(ta, a0, a1);
        upk2(tb, b0, b1);
        upk2(tc, c0, c1);
        sA += ex2f(a0);
        sB += ex2f(a1);
        sC += ex2f(b0);
        sD += ex2f(b1);
        sE += ex2f(c0);
        sF += ex2f(c1);

        // 1 pair via packed polynomial exp2
        float d0, d1;
        upk2(td, d0, d1);
        d0 = fmaxf(d0, -125.0f);        // underflow clamp (FMNMX, alu pipe)
        d1 = fmaxf(d1, -125.0f);
        u64 tdc = pk2(d0, d1);
        u64 k2 = add2(tdc, MG);         // round-to-nearest in mantissa
        u64 n2 = add2(k2, NMG);         // n = rint(t)
        u64 f2 = fma2(NONE, n2, tdc);   // f = t - n in [-0.5, 0.5]
        u64 p2 = fma2(C5, f2, C4);
        p2 = fma2(p2, f2, C3);
        p2 = fma2(p2, f2, C2);
        p2 = fma2(p2, f2, C1);
        p2 = fma2(p2, f2, C0);
        float kf0, kf1;
        upk2(k2, kf0, kf1);
        int s0b = (__float_as_int(kf0) << 23) + 0x3F800000;  // 2^n bits
        int s1b = (__float_as_int(kf1) << 23) + 0x3F800000;
        u64 s2 = pk2(__int_as_float(s0b), __int_as_float(s1b));
        accP = fma2(p2, s2, accP);      // acc += poly * 2^n
    }

    float p0, p1;
    upk2(accP, p0, p1);
    return ((sA + sB) + (sC + sD)) + ((sE + sF) + (p0 + p1));
}

// grid = (M/64, B), 64 threads. Fused: stage+preprocess samples in smem,
// per-thread point constants, hybrid MUFU/poly exp2 mainloop.
__global__ __launch_bounds__(64)
void kde_main_kernel(const float* __restrict__ inputs,
                     const float* __restrict__ pts,
                     float* __restrict__ out,
                     int N, int M, float gamma2, float scale_out) {
    const int b = blockIdx.y;
    const int m = blockIdx.x * 64 + threadIdx.x;

    __shared__ __align__(16) float sxx[2048];
    __shared__ __align__(16) float sxy[2048];
    __shared__ __align__(16) float ssn[2048];

    // Stage + preprocess samples of batch b: (N,2) -> SoA (xx, xy, -g2*|x|^2)
    {
        const float4* src = (const float4*)(inputs + (size_t)b * N * 2);
        const int nv = N >> 1;          // float4s, 2 samples each
        for (int j = threadIdx.x; j < nv; j += 64) {
            float4 v = src[j];
            int n0 = 2 * j;
            sxx[n0]     = v.x;  sxy[n0]     = v.y;
            ssn[n0]     = -gamma2 * fmaf(v.x, v.x, v.y * v.y);
            sxx[n0 + 1] = v.z;  sxy[n0 + 1] = v.w;
            ssn[n0 + 1] = -gamma2 * fmaf(v.z, v.z, v.w * v.w);
        }
    }

    // Point constants (log2 units): arg = am2 + qx*xx + qy*xy + sn
    const float px = pts[2 * m], py = pts[2 * m + 1];
    const float qxs = 2.0f * gamma2 * px;
    const float qys = 2.0f * gamma2 * py;
    const float am2s = -gamma2 * fmaf(px, px, py * py);

    __syncthreads();

    const u64 qx2  = pk2(qxs, qxs);
    const u64 qy2  = pk2(qys, qys);
    const u64 am22 = pk2(am2s, am2s);

    const ulonglong2* hx = (const ulonglong2*)sxx;
    const ulonglong2* hy = (const ulonglong2*)sxy;
    const ulonglong2* hs = (const ulonglong2*)ssn;
    const int nq = N >> 3;

    // Fast path factors exp2(am2) out of the loop; safe while exp2(-am2)
    // can't overflow the accumulators (am2 >= -100). Warp-uniform branch.
    const bool fast = __all_sync(0xffffffffu, am2s >= -100.0f);

    float total, fin_scale;
    if (fast) {
        total = kde_loop<false>(hx, hy, hs, qx2, qy2, am22, nq);
        fin_scale = scale_out * ex2f(am2s);
    } else {
        total = kde_loop<true>(hx, hy, hs, qx2, qy2, am22, nq);
        fin_scale = scale_out;
    }

    out[(size_t)b * M + m] = total * fin_scale;
}

extern "C" void kernel_launch(void* const* d_in, const int* in_sizes, int n_in,
                              void* d_out, int out_size) {
    const float* inputs = (const float*)d_in[0];   // (B, N, 2) float32
    const float* pts    = (const float*)d_in[1];   // (M, 2) float32
    float* out          = (float*)d_out;           // (B, M) float32

    const int d = 2;
    const int M  = in_sizes[1] / d;                // 512
    const int BN = in_sizes[0] / d;                // B*N
    const int B  = out_size / M;                   // 128
    const int N  = BN / B;                         // 2048

    // Silverman bandwidth (d=2)
    double h = pow(4.0 / (d + 2), 1.0 / (d + 4)) * pow((double)N, -1.0 / (d + 4));
    double coef = 1.0 / pow(2.0 * M_PI * h * h, d / 2.0);
    double gamma = 0.5 / (h * h);
    float gamma2 = (float)(gamma * 1.4426950408889634);  // fold 1/ln2 for ex2
    float scale_out = (float)(coef / (double)N);

    dim3 grid(M / 64, B);   // (8, 128) = 1024 blocks, 64 threads
    kde_main_kernel<<<grid, 64>>>(inputs, pts, out, N, M, gamma2, scale_out);
}

// round 8
// speedup vs baseline: 1.0553x; 1.0553x over previous
#include <cuda_runtime.h>
#include <math.h>

typedef unsigned long long u64;

#define ZSPLIT 2

// Partial sums scratch: (ZSPLIT, B*M) — no allocation allowed.
__device__ float g_part[ZSPLIT][128 * 512];

__device__ __forceinline__ void upk2(u64 v, float& lo, float& hi) {
    asm("mov.b64 {%0, %1}, %2;" : "=f"(lo), "=f"(hi) : "l"(v));
}
__device__ __forceinline__ u64 pk2(float lo, float hi) {
    u64 r; asm("mov.b64 %0, {%1, %2};" : "=l"(r) : "f"(lo), "f"(hi)); return r;
}
__device__ __forceinline__ u64 fma2(u64 a, u64 b, u64 c) {
    u64 d; asm("fma.rn.f32x2 %0, %1, %2, %3;" : "=l"(d) : "l"(a), "l"(b), "l"(c)); return d;
}
__device__ __forceinline__ u64 add2(u64 a, u64 b) {
    u64 d; asm("add.rn.f32x2 %0, %1, %2;" : "=l"(d) : "l"(a), "l"(b)); return d;
}
__device__ __forceinline__ float ex2f(float x) {
    float e; asm("ex2.approx.ftz.f32 %0, %1;" : "=f"(e) : "f"(x)); return e;
}

#define MAGIC_F 12582912.0f   // 1.5 * 2^23

// Mainloop over the block's sample chunk; ADD_AM2 selects slow (3-op dot) path.
template <bool ADD_AM2>
__device__ __forceinline__ float kde_loop(
    const ulonglong2* __restrict__ hx,
    const ulonglong2* __restrict__ hy,
    const ulonglong2* __restrict__ hs,
    u64 qx2, u64 qy2, u64 am22, int nq)
{
    const u64 C0 = pk2(1.0f, 1.0f);
    const u64 C1 = pk2(0.69314718056f, 0.69314718056f);
    const u64 C2 = pk2(0.24022650696f, 0.24022650696f);
    const u64 C3 = pk2(0.05550410866f, 0.05550410866f);
    const u64 C4 = pk2(0.00961812911f, 0.00961812911f);
    const u64 C5 = pk2(0.00133335581f, 0.00133335581f);
    const u64 MG   = pk2(MAGIC_F, MAGIC_F);
    const u64 NMG  = pk2(-MAGIC_F, -MAGIC_F);
    const u64 NONE = pk2(-1.0f, -1.0f);

    float sA = 0.f, sB = 0.f, sC = 0.f, sD = 0.f, sE = 0.f, sF = 0.f;
    u64 accP = 0ull;

    #pragma unroll 4
    for (int q = 0; q < nq; q++) {
        int j = 2 * q;
        ulonglong2 X0 = hx[j], X1 = hx[j + 1];
        ulonglong2 Y0 = hy[j], Y1 = hy[j + 1];
        ulonglong2 S0 = hs[j], S1 = hs[j + 1];

        // dot products: 2 packed fma per pair (3rd add only on slow path)
        u64 ta = fma2(qx2, X0.x, S0.x); ta = fma2(qy2, Y0.x, ta);
        u64 tb = fma2(qx2, X0.y, S0.y); tb = fma2(qy2, Y0.y, tb);
        u64 tc = fma2(qx2, X1.x, S1.x); tc = fma2(qy2, Y1.x, tc);
        u64 td = fma2(qx2, X1.y, S1.y); td = fma2(qy2, Y1.y, td);
        if (ADD_AM2) {
            ta = add2(ta, am22);
            tb = add2(tb, am22);
            tc = add2(tc, am22);
            td = add2(td, am22);
        }

        // 3 pairs via MUFU ex2, scalar-FADD accumulate
        float a0, a1, b0, b1, c0, c1;
        upk2(ta, a0, a1);
        upk2(tb, b0, b1);
        upk2(tc, c0, c1);
        sA += ex2f(a0);
        sB += ex2f(a1);
        sC += ex2f(b0);
        sD += ex2f(b1);
        sE += ex2f(c0);
        sF += ex2f(c1);

        // 1 pair via packed polynomial exp2 (FMA + ALU pipes)
        float d0, d1;
        upk2(td, d0, d1);
        d0 = fmaxf(d0, -125.0f);
        d1 = fmaxf(d1, -125.0f);
        u64 tdc = pk2(d0, d1);
        u64 k2 = add2(tdc, MG);         // round-to-nearest in mantissa
        u64 n2 = add2(k2, NMG);         // n = rint(t)
        u64 f2 = fma2(NONE, n2, tdc);   // f = t - n in [-0.5, 0.5]
        u64 p2 = fma2(C5, f2, C4);
        p2 = fma2(p2, f2, C3);
        p2 = fma2(p2, f2, C2);
        p2 = fma2(p2, f2, C1);
        p2 = fma2(p2, f2, C0);
        float kf0, kf1;
        upk2(k2, kf0, kf1);
        int s0b = (__float_as_int(kf0) << 23) + 0x3F800000;  // 2^n bits
        int s1b = (__float_as_int(kf1) << 23) + 0x3F800000;
        u64 s2 = pk2(__int_as_float(s0b), __int_as_float(s1b));
        accP = fma2(p2, s2, accP);
    }

    float p0, p1;
    upk2(accP, p0, p1);
    return ((sA + sB) + (sC + sD)) + ((sE + sF) + (p0 + p1));
}

// grid = (M/64, B, ZSPLIT), 64 threads. Each block handles N/ZSPLIT samples
// and writes a scaled partial to g_part[z].
__global__ __launch_bounds__(64)
void kde_main_kernel(const float* __restrict__ inputs,
                     const float* __restrict__ pts,
                     int N, int M, float gamma2, float scale_out) {
    const int b = blockIdx.y;
    const int z = blockIdx.z;
    const int m = blockIdx.x * 64 + threadIdx.x;
    const int Nc = N / ZSPLIT;   // samples per block

    __shared__ __align__(16) float sxx[2048 / ZSPLIT];
    __shared__ __align__(16) float sxy[2048 / ZSPLIT];
    __shared__ __align__(16) float ssn[2048 / ZSPLIT];

    // Stage + preprocess this block's chunk: (Nc,2) -> SoA (xx, xy, -g2*|x|^2)
    {
        const float4* src = (const float4*)(inputs + (size_t)b * N * 2
                                                   + (size_t)z * Nc * 2);
        const int nv = Nc >> 1;          // float4s, 2 samples each
        for (int j = threadIdx.x; j < nv; j += 64) {
            float4 v = src[j];
            int n0 = 2 * j;
            sxx[n0]     = v.x;  sxy[n0]     = v.y;
            ssn[n0]     = -gamma2 * fmaf(v.x, v.x, v.y * v.y);
            sxx[n0 + 1] = v.z;  sxy[n0 + 1] = v.w;
            ssn[n0 + 1] = -gamma2 * fmaf(v.z, v.z, v.w * v.w);
        }
    }

    // Point constants (log2 units): arg = am2 + qx*xx + qy*xy + sn
    const float px = pts[2 * m], py = pts[2 * m + 1];
    const float qxs = 2.0f * gamma2 * px;
    const float qys = 2.0f * gamma2 * py;
    const float am2s = -gamma2 * fmaf(px, px, py * py);

    __syncthreads();

    const u64 qx2  = pk2(qxs, qxs);
    const u64 qy2  = pk2(qys, qys);
    const u64 am22 = pk2(am2s, am2s);

    const ulonglong2* hx = (const ulonglong2*)sxx;
    const ulonglong2* hy = (const ulonglong2*)sxy;
    const ulonglong2* hs = (const ulonglong2*)ssn;
    const int nq = Nc >> 3;

    // Fast path factors exp2(am2) out of the loop (safe for am2 >= -100:
    // sum <= Nc * 2^100 << FLT_MAX). Warp-uniform branch.
    const bool fast = __all_sync(0xffffffffu, am2s >= -100.0f);

    float total, fin_scale;
    if (fast) {
        total = kde_loop<false>(hx, hy, hs, qx2, qy2, am22, nq);
        fin_scale = scale_out * ex2f(am2s);
    } else {
        total = kde_loop<true>(hx, hy, hs, qx2, qy2, am22, nq);
        fin_scale = scale_out;
    }

    g_part[z][(size_t)b * M + m] = total * fin_scale;
}

// Sum the ZSPLIT partial planes into the output.
__global__ void kde_reduce_kernel(float* __restrict__ out, int total) {
    int i = blockIdx.x * blockDim.x + threadIdx.x;
    if (i < total) {
        float s = g_part[0][i];
        #pragma unroll
        for (int z = 1; z < ZSPLIT; z++) s += g_part[z][i];
        out[i] = s;
    }
}

extern "C" void kernel_launch(void* const* d_in, const int* in_sizes, int n_in,
                              void* d_out, int out_size) {
    const float* inputs = (const float*)d_in[0];   // (B, N, 2) float32
    const float* pts    = (const float*)d_in[1];   // (M, 2) float32
    float* out          = (float*)d_out;           // (B, M) float32

    const int d = 2;
    const int M  = in_sizes[1] / d;                // 512
    const int BN = in_sizes[0] / d;                // B*N
    const int B  = out_size / M;                   // 128
    const int N  = BN / B;                         // 2048

    // Silverman bandwidth (d=2)
    double h = pow(4.0 / (d + 2), 1.0 / (d + 4)) * pow((double)N, -1.0 / (d + 4));
    double coef = 1.0 / pow(2.0 * M_PI * h * h, d / 2.0);
    double gamma = 0.5 / (h * h);
    float gamma2 = (float)(gamma * 1.4426950408889634);  // fold 1/ln2 for ex2
    float scale_out = (float)(coef / (double)N);

    {
        dim3 grid(M / 64, B, ZSPLIT);   // (8, 128, 2) = 2048 blocks
        kde_main_kernel<<<grid, 64>>>(inputs, pts, N, M, gamma2, scale_out);
    }
    {
        int total = B * M;
        kde_reduce_kernel<<<(total + 255) / 256, 256>>>(out, total);
    }
}